// round 9
// baseline (speedup 1.0000x reference)
#include <cuda_runtime.h>
#include <cstdint>

#define Bb 8
#define Tt 2048
#define Vv 1024
#define BM 128
#define BN 128
#define BK 32
#define NTH 128
#define BUFB 32768

// k-permutation within each 32-col block: c(k) = (k&3)*8 + (k>>2)
#define CPERM(w) ((((w) & 3) << 3) | ((w) >> 2))

// ---- scratch (static __device__ — no allocations allowed) ----
__device__ float g_WkT[Vv * Vv];                // k(=o)-permuted cols
__device__ float g_WqT[Vv * Vv];                // k(=o)-permuted cols
__device__ float g_WvT[Vv * Vv];                // normal
__device__ float g_pv[Tt];
__device__ float g_CT[Vv * Vv];                 // CT[i][a], normal cols
__device__ float g_Cg[(size_t)Bb * Vv * Tt];    // Cg[b][a][s'], s'-permuted
__device__ float g_Gv[(size_t)Bb * Vv * Tt];    // Gv[b][o][s],  s-permuted
__device__ float g_Ah[(size_t)Bb * Vv * Tt];    // Ah[b][a][s],  s-permuted

// ---------------- helpers ----------------
__device__ __forceinline__ uint32_t smem_u32(const void* p) {
    uint32_t a;
    asm("{ .reg .u64 t; cvta.to.shared.u64 t, %1; cvt.u32.u64 %0, t; }" : "=r"(a) : "l"(p));
    return a;
}
__device__ __forceinline__ float tf32r(float x) {
    unsigned u;
    asm("cvt.rna.tf32.f32 %0, %1;" : "=r"(u) : "f"(x));
    return __uint_as_float(u);
}
__device__ __forceinline__ void cpa16(uint32_t dst, const void* src) {
    asm volatile("cp.async.cg.shared.global [%0], [%1], 16;" :: "r"(dst), "l"(src) : "memory");
}
#define CP_COMMIT() asm volatile("cp.async.commit_group;" ::: "memory")
#define CP_WAIT1()  asm volatile("cp.async.wait_group 1;" ::: "memory")
#define CP_WAIT0()  asm volatile("cp.async.wait_group 0;" ::: "memory")

__device__ __forceinline__ void mma_tf32(float* c, float a0, float a1, float a2, float a3,
                                         float b0, float b1) {
    asm volatile(
        "mma.sync.aligned.m16n8k8.row.col.f32.tf32.tf32.f32 "
        "{%0,%1,%2,%3}, {%4,%5,%6,%7}, {%8,%9}, {%0,%1,%2,%3};"
        : "+f"(c[0]), "+f"(c[1]), "+f"(c[2]), "+f"(c[3])
        : "r"(__float_as_uint(a0)), "r"(__float_as_uint(a1)),
          "r"(__float_as_uint(a2)), "r"(__float_as_uint(a3)),
          "r"(__float_as_uint(b0)), "r"(__float_as_uint(b1)));
}

// ---------------- MMA core: one BK=32 chunk, warp tile 64x64 ----------------
// smem tile [row][c] with c = k-permuted; thread kq's 8 k-values are the 8
// contiguous floats at byte kq*32 (^ swizzle) -> two LDS.128 per row per chunk.
__device__ __forceinline__ void mma_chunk(const char* Atp, const char* Btp,
                                          const uint32_t* ko2, float acc[4][8][4]) {
#pragma unroll
    for (int half = 0; half < 2; half++) {
        float4 af[8];
#pragma unroll
        for (int mf = 0; mf < 4; mf++) {
            af[mf * 2]     = *(const float4*)(Atp + mf * 2048 +        ko2[half]);
            af[mf * 2 + 1] = *(const float4*)(Atp + mf * 2048 + 1024 + ko2[half]);
        }
        float4 bf[8];
#pragma unroll
        for (int nf = 0; nf < 8; nf++)
            bf[nf] = *(const float4*)(Btp + nf * 1024 + ko2[half]);
#pragma unroll
        for (int gg = 0; gg < 2; gg++) {
#pragma unroll
            for (int nf = 0; nf < 8; nf++) {
                const float b0 = gg ? bf[nf].z : bf[nf].x;
                const float b1 = gg ? bf[nf].w : bf[nf].y;
#pragma unroll
                for (int mf = 0; mf < 4; mf++) {
                    const float a0 = gg ? af[mf*2].z   : af[mf*2].x;
                    const float a1 = gg ? af[mf*2+1].z : af[mf*2+1].x;
                    const float a2 = gg ? af[mf*2].w   : af[mf*2].y;
                    const float a3 = gg ? af[mf*2+1].w : af[mf*2+1].y;
                    mma_tf32(acc[mf][nf], a0, a1, a2, a3, b0, b1);
                }
            }
        }
    }
}

#define GEMM_PROLOG() \
    extern __shared__ char dsm[]; \
    const int tid = threadIdx.x; \
    const int wid = tid >> 5, lane = tid & 31; \
    const int gid = lane >> 2, kq = lane & 3; \
    const int wm = (wid & 1) * 64, wn = (wid >> 1) * 64; \
    uint32_t ko2[2]; \
    { const uint32_t xg = (uint32_t)(gid & 7) << 4; \
      ko2[0] = ((uint32_t)(kq * 32)) ^ xg; \
      ko2[1] = ((uint32_t)(kq * 32 + 16)) ^ xg; } \
    const char* Abase = dsm + (wm + gid) * 128; \
    const char* Bbase = dsm + 16384 + (wn + gid) * 128; \
    char* fAp = dsm + tid * 128; \
    char* fBp = fAp + 16384; \
    const uint32_t fA = smem_u32(fAp); \
    const uint32_t fB = fA + 16384; \
    const uint32_t fxg = (uint32_t)(tid & 7) << 4; \
    (void)fBp; (void)fB; \
    float acc[4][8][4]; \
    _Pragma("unroll") for (int mf = 0; mf < 4; mf++) \
    _Pragma("unroll") for (int nf = 0; nf < 8; nf++) \
    _Pragma("unroll") for (int c = 0; c < 4; c++) acc[mf][nf][c] = 0.f;

// triple-buffered mainloop: fill 2 ahead, one sync per chunk
#define GEMM_LOOP(nt, FILL) \
    FILL(0, 0u); CP_COMMIT(); \
    FILL(1, (uint32_t)BUFB); CP_COMMIT(); \
    { int p = 0; \
      for (int kt = 0; kt < (nt); kt++) { \
          if (kt + 1 < (nt)) CP_WAIT1(); else CP_WAIT0(); \
          __syncthreads(); \
          if (kt + 2 < (nt)) { \
              const int p2 = (p >= 1) ? p - 1 : 2; \
              FILL(kt + 2, (uint32_t)(p2 * BUFB)); CP_COMMIT(); \
          } \
          mma_chunk(Abase + p * BUFB, Bbase + p * BUFB, ko2, acc); \
          p = (p == 2) ? 0 : p + 1; \
      } }

#define GEMM_EPI(dstptr, ldT, ROWBASE, COLBASE, XF) \
    _Pragma("unroll") for (int mf = 0; mf < 4; mf++) \
    _Pragma("unroll") for (int h = 0; h < 2; h++) { \
        const int row_ = (ROWBASE) + wm + mf * 16 + gid + 8 * h; \
        float* orow_ = (dstptr) + (size_t)row_ * (ldT) + (COLBASE) + wn; \
        _Pragma("unroll") for (int nf = 0; nf < 8; nf++) \
            *(float2*)&orow_[nf * 8 + kq * 2] = \
                make_float2(XF(acc[mf][nf][2 * h]), XF(acc[mf][nf][2 * h + 1])); }

// epilogue with k-permuted column storage (for tiles consumed as K downstream)
#define GEMM_EPI_PERM(dstptr, ldT, ROWBASE, COLBASE, XF) \
    _Pragma("unroll") for (int mf = 0; mf < 4; mf++) \
    _Pragma("unroll") for (int h = 0; h < 2; h++) { \
        const int row_ = (ROWBASE) + wm + mf * 16 + gid + 8 * h; \
        float* orow_ = (dstptr) + (size_t)row_ * (ldT) + (COLBASE); \
        _Pragma("unroll") for (int nf = 0; nf < 8; nf++) \
        _Pragma("unroll") for (int cc = 0; cc < 2; cc++) { \
            const int sl_ = wn + nf * 8 + kq * 2 + cc; \
            orow_[(sl_ & ~31) | CPERM(sl_ & 31)] = XF(acc[mf][nf][2 * h + cc]); } }

#define XF_TF(x)  tf32r(x)
#define XF_OUT(x) ((x) + 0.001f)

// ---------------- prep kernels ----------------
__global__ void round_pv(const float* __restrict__ pv) {
    int i = blockIdx.x * 1024 + threadIdx.x;
    g_pv[i] = tf32r(pv[i]);
}

// WkT/WqT stored with k(=o)-permuted columns; WvT normal.
__global__ void transpose3(const float* __restrict__ Wk,
                           const float* __restrict__ Wq,
                           const float* __restrict__ Wv) {
    __shared__ float tile[32][33];
    const float* src;
    float* dst;
    bool perm;
    if (blockIdx.z == 0)      { src = Wk; dst = g_WkT; perm = true; }
    else if (blockIdx.z == 1) { src = Wq; dst = g_WqT; perm = true; }
    else                      { src = Wv; dst = g_WvT; perm = false; }
    int x = blockIdx.x * 32 + threadIdx.x;
    int y = blockIdx.y * 32 + threadIdx.y;
#pragma unroll
    for (int i = 0; i < 32; i += 8)
        tile[threadIdx.y + i][threadIdx.x] = src[(size_t)(y + i) * Vv + x];
    __syncthreads();
    const int tx = threadIdx.x;
    const int xcol = blockIdx.y * 32 + (perm ? CPERM(tx) : tx);
    const int y2 = blockIdx.x * 32 + threadIdx.y;
#pragma unroll
    for (int i = 0; i < 32; i += 8)
        dst[(size_t)(y2 + i) * Vv + xcol] = tf32r(tile[tx][threadIdx.y + i]);
}

// Gv[b][o][s] = WvT[idx[b][s]][o]   (z even) — s-permuted cols
// Cg[b][a][s'] = CT[idx[b][s']][a]  (z odd)  — s'-permuted cols
__global__ void gather2(const int* __restrict__ idx) {
    __shared__ float tile[32][33];
    const int z = blockIdx.z;
    const int b = z >> 1;
    const float* WT = (z & 1) ? g_CT : g_WvT;
    float* G        = (z & 1) ? g_Cg : g_Gv;
    const int o0 = blockIdx.x * 32, s0 = blockIdx.y * 32;
    const int tx = threadIdx.x, ty = threadIdx.y;
#pragma unroll
    for (int i = 0; i < 32; i += 8) {
        const int row = idx[b * Tt + s0 + ty + i];
        tile[ty + i][tx] = WT[(size_t)row * Vv + o0 + tx];
    }
    __syncthreads();
    const int scol = s0 + CPERM(tx);
#pragma unroll
    for (int i = 0; i < 32; i += 8)
        G[((size_t)(b * Vv + o0 + ty + i)) * Tt + scol] = tile[tx][ty + i];
}

// ---------------------------------------------------------------------------
// Kernel A: CT[i][a] = sum_o WkT[i][o] * WqT[a][o]   (inputs k-permuted)
// ---------------------------------------------------------------------------
__global__ __launch_bounds__(NTH)
void kernel_CT() {
    const int i0 = blockIdx.y * BM;
    const int a0 = blockIdx.x * BN;
    GEMM_PROLOG();
    const float* as = g_WkT + (size_t)(i0 + tid) * Vv;
    const float* bs = g_WqT + (size_t)(a0 + tid) * Vv;
    auto fill = [&](int kt, uint32_t bo) {
        const int o0 = kt * BK;
#pragma unroll
        for (int ch = 0; ch < 8; ch++) {
            const uint32_t off = bo + (((uint32_t)(ch * 16)) ^ fxg);
            cpa16(fA + off, as + o0 + ch * 4);
            cpa16(fB + off, bs + o0 + ch * 4);
        }
    };
    const int nt = Vv / BK;
    GEMM_LOOP(nt, fill);
    GEMM_EPI(g_CT, Vv, i0, a0, XF_TF);
}

// ---------------------------------------------------------------------------
// Kernel B: Ah[b][a][s] = sum_{s'<=s} Cg[b][a][s'] * pv[s-s']   (causal Toeplitz)
// A = Cg (pre-permuted, cp.async). B generated directly in permuted order.
// Epilogue stores s-permuted (consumed as K by kernel C).
// ---------------------------------------------------------------------------
__global__ __launch_bounds__(NTH)
void kernel_Ah() {
    const int b  = blockIdx.z;
    const int a0 = blockIdx.y * BM;
    const int s0 = blockIdx.x * BN;
    GEMM_PROLOG();
    const float* as = g_Cg + ((size_t)(b * Vv + a0 + tid)) * Tt;
    const int s = s0 + tid;   // this thread's generated B row
    auto fill = [&](int kt, uint32_t bo) {
        const int sp0 = kt * BK;
#pragma unroll
        for (int ch = 0; ch < 8; ch++) {
            const uint32_t off = bo + (((uint32_t)(ch * 16)) ^ fxg);
            cpa16(fA + off, as + sp0 + ch * 4);
            // permuted generation: chunk ch holds k = kb, kb+4, kb+8, kb+12
            const int kb = (ch & 1) * 16 + (ch >> 1);
            const int d = s - (sp0 + kb);
            float4 v;
            v.x = (d      >= 0) ? g_pv[d]      : 0.f;
            v.y = (d - 4  >= 0) ? g_pv[d - 4]  : 0.f;
            v.z = (d - 8  >= 0) ? g_pv[d - 8]  : 0.f;
            v.w = (d - 12 >= 0) ? g_pv[d - 12] : 0.f;
            *(float4*)(fBp + off) = v;
        }
    };
    const int nt = s0 / BK + BN / BK;
    GEMM_LOOP(nt, fill);
    GEMM_EPI_PERM(g_Ah + (size_t)b * Vv * Tt, Tt, a0, s0, XF_TF);
}

// ---------------------------------------------------------------------------
// Kernel C: out[b][t][o] = 1e-3 + sum_{s<=t} Ah[b][idx[b][t]][s] * Gv[b][o][s]
// A = Ah rows (pre-permuted); diagonal region masked per permuted k values.
// B = Gv (pre-permuted). Output epilogue normal.
// ---------------------------------------------------------------------------
__global__ __launch_bounds__(NTH)
void kernel_out(const int* __restrict__ idx, float* __restrict__ out) {
    const int b  = blockIdx.z;
    const int t0 = blockIdx.y * BM;
    const int n0 = blockIdx.x * BN;
    GEMM_PROLOG();
    const int t = t0 + tid;
    const int ia = idx[b * Tt + t];
    const float* as = g_Ah + ((size_t)(b * Vv + ia)) * Tt;
    const float* bs = g_Gv + ((size_t)(b * Vv + n0 + tid)) * Tt;
    const int nt = t0 / BK + BN / BK;
    auto fill = [&](int kt, uint32_t bo) {
        const int sp0 = kt * BK;
        if (kt >= nt - 4) {
            // diagonal region: manual masked A fill (permuted positions)
#pragma unroll
            for (int ch = 0; ch < 8; ch++) {
                const uint32_t off = bo + (((uint32_t)(ch * 16)) ^ fxg);
                const int kb = (ch & 1) * 16 + (ch >> 1);
                const int sb = sp0 + kb;
                float4 v = *(const float4*)(as + sp0 + ch * 4);
                v.x = (sb      <= t) ? v.x : 0.f;
                v.y = (sb + 4  <= t) ? v.y : 0.f;
                v.z = (sb + 8  <= t) ? v.z : 0.f;
                v.w = (sb + 12 <= t) ? v.w : 0.f;
                *(float4*)(fAp + off) = v;
                cpa16(fB + off, bs + sp0 + ch * 4);
            }
        } else {
#pragma unroll
            for (int ch = 0; ch < 8; ch++) {
                const uint32_t off = bo + (((uint32_t)(ch * 16)) ^ fxg);
                cpa16(fA + off, as + sp0 + ch * 4);
                cpa16(fB + off, bs + sp0 + ch * 4);
            }
        }
    };
    GEMM_LOOP(nt, fill);
    GEMM_EPI(out + (size_t)b * Tt * Vv, Vv, t0, n0, XF_OUT);
}

// ---------------------------------------------------------------------------
extern "C" void kernel_launch(void* const* d_in, const int* in_sizes, int n_in,
                              void* d_out, int out_size) {
    const int*   idx = (const int*)d_in[0];
    const float* pv  = (const float*)d_in[1];
    const float* Wk  = (const float*)d_in[2];
    const float* Wq  = (const float*)d_in[3];
    const float* Wv  = (const float*)d_in[4];
    float* out = (float*)d_out;

    const int dynsmem = 3 * BUFB;  // 96 KB
    cudaFuncSetAttribute(kernel_CT,  cudaFuncAttributeMaxDynamicSharedMemorySize, dynsmem);
    cudaFuncSetAttribute(kernel_Ah,  cudaFuncAttributeMaxDynamicSharedMemorySize, dynsmem);
    cudaFuncSetAttribute(kernel_out, cudaFuncAttributeMaxDynamicSharedMemorySize, dynsmem);

    round_pv  <<<Tt / 1024, 1024>>>(pv);
    transpose3<<<dim3(Vv / 32, Vv / 32, 3), dim3(32, 8)>>>(Wk, Wq, Wv);
    kernel_CT <<<dim3(Vv / BN, Vv / BM, 1), NTH, dynsmem>>>();
    gather2   <<<dim3(Vv / 32, Tt / 32, Bb * 2), dim3(32, 8)>>>(idx);
    kernel_Ah <<<dim3(Tt / BN, Vv / BM, Bb), NTH, dynsmem>>>();
    kernel_out<<<dim3(Vv / BN, Tt / BM, Bb), NTH, dynsmem>>>(idx, out);
}

// round 10
// speedup vs baseline: 1.0529x; 1.0529x over previous
#include <cuda_runtime.h>
#include <cstdint>

#define Bb 8
#define Tt 2048
#define Vv 1024
#define BM 128
#define BN 128
#define BK 32
#define NTH 128
#define BUFB 32768

// ---- scratch (static __device__ — no allocations allowed) ----
__device__ float g_WkT[Vv * Vv];
__device__ float g_WqT[Vv * Vv];
__device__ float g_WvT[Vv * Vv];
__device__ float g_pv[Tt];
__device__ float g_CT[Vv * Vv];                 // CT[i][a] = (Wq^T Wk)[a][i]
__device__ float g_Cg[(size_t)Bb * Vv * Tt];    // Cg[b][a][s'] = CT[idx[b][s']][a]
__device__ float g_Gv[(size_t)Bb * Vv * Tt];    // Gv[b][o][s]  = WvT[idx[b][s]][o]
__device__ float g_Ah[(size_t)Bb * Vv * Tt];    // Ah[b][a][s]

// ---------------- helpers ----------------
__device__ __forceinline__ uint32_t smem_u32(const void* p) {
    uint32_t a;
    asm("{ .reg .u64 t; cvta.to.shared.u64 t, %1; cvt.u32.u64 %0, t; }" : "=r"(a) : "l"(p));
    return a;
}
__device__ __forceinline__ float tf32r(float x) {
    unsigned u;
    asm("cvt.rna.tf32.f32 %0, %1;" : "=r"(u) : "f"(x));
    return __uint_as_float(u);
}
__device__ __forceinline__ void cpa16(uint32_t dst, const void* src) {
    asm volatile("cp.async.cg.shared.global [%0], [%1], 16;" :: "r"(dst), "l"(src) : "memory");
}
#define CP_COMMIT() asm volatile("cp.async.commit_group;" ::: "memory")
#define CP_WAIT0()  asm volatile("cp.async.wait_group 0;" ::: "memory")

__device__ __forceinline__ void mma_tf32(float* c, const float* a, float b0, float b1) {
    asm volatile(
        "mma.sync.aligned.m16n8k8.row.col.f32.tf32.tf32.f32 "
        "{%0,%1,%2,%3}, {%4,%5,%6,%7}, {%8,%9}, {%0,%1,%2,%3};"
        : "+f"(c[0]), "+f"(c[1]), "+f"(c[2]), "+f"(c[3])
        : "r"(__float_as_uint(a[0])), "r"(__float_as_uint(a[1])),
          "r"(__float_as_uint(a[2])), "r"(__float_as_uint(a[3])),
          "r"(__float_as_uint(b0)), "r"(__float_as_uint(b1)));
}

// ---------------- MMA core: one BK=32 chunk, warp tile 64x64 ----------------
// Tile layout [row][k], 128B rows, swizzle folded into ko[] (bank-conflict-free).
__device__ __forceinline__ void mma_chunk(const char* Atp, const char* Btp,
                                          const uint32_t* ko, float acc[4][8][4]) {
#pragma unroll
    for (int k8 = 0; k8 < 4; k8++) {
        const char* a0p = Atp + ko[k8 * 2 + 0];
        const char* a1p = Atp + ko[k8 * 2 + 1];
        const char* b0p = Btp + ko[k8 * 2 + 0];
        const char* b1p = Btp + ko[k8 * 2 + 1];
        float a[4][4];
#pragma unroll
        for (int mf = 0; mf < 4; mf++) {
            a[mf][0] = *(const float*)(a0p + mf * 2048);
            a[mf][1] = *(const float*)(a0p + mf * 2048 + 1024);
            a[mf][2] = *(const float*)(a1p + mf * 2048);
            a[mf][3] = *(const float*)(a1p + mf * 2048 + 1024);
        }
#pragma unroll
        for (int nf = 0; nf < 8; nf++) {
            const float b0 = *(const float*)(b0p + nf * 1024);
            const float b1 = *(const float*)(b1p + nf * 1024);
#pragma unroll
            for (int mf = 0; mf < 4; mf++)
                mma_tf32(acc[mf][nf], a[mf], b0, b1);
        }
    }
}

#define GEMM_PROLOG() \
    extern __shared__ char dsm[]; \
    const int tid = threadIdx.x; \
    const int wid = tid >> 5, lane = tid & 31; \
    const int gid = lane >> 2, kq = lane & 3; \
    const int wm = (wid & 1) * 64, wn = (wid >> 1) * 64; \
    uint32_t ko[8]; \
    { const uint32_t xg = (uint32_t)(gid & 7) << 4; \
      _Pragma("unroll") for (int k8 = 0; k8 < 4; k8++) \
      _Pragma("unroll") for (int h = 0; h < 2; h++) \
          ko[k8 * 2 + h] = ((uint32_t)((k8 * 8 + kq + h * 4) * 4)) ^ xg; } \
    const char* Abase = dsm + (wm + gid) * 128; \
    const char* Bbase = dsm + 16384 + (wn + gid) * 128; \
    char* fAp = dsm + tid * 128; \
    char* fBp = fAp + 16384; \
    const uint32_t fA = smem_u32(fAp); \
    const uint32_t fB = fA + 16384; \
    const uint32_t fxg = (uint32_t)(tid & 7) << 4; \
    (void)fBp; (void)fB; \
    float acc[4][8][4]; \
    _Pragma("unroll") for (int mf = 0; mf < 4; mf++) \
    _Pragma("unroll") for (int nf = 0; nf < 8; nf++) \
    _Pragma("unroll") for (int c = 0; c < 4; c++) acc[mf][nf][c] = 0.f;

// 2-stage pipeline: fill(kt+1) issued after sync, overlaps mma(kt).
// sync at iter kt guarantees all warps finished mma(kt-1) (which used buf p^1)
// before fill(kt+1) overwrites it.
#define GEMM_LOOP(nt, FILL) \
    FILL(0, 0u); CP_COMMIT(); \
    { int p = 0; \
      for (int kt = 0; kt < (nt); kt++) { \
          CP_WAIT0(); \
          __syncthreads(); \
          if (kt + 1 < (nt)) { \
              FILL(kt + 1, (uint32_t)((p ^ 1) * BUFB)); CP_COMMIT(); \
          } \
          mma_chunk(Abase + p * BUFB, Bbase + p * BUFB, ko, acc); \
          p ^= 1; \
      } }

#define GEMM_EPI(dstptr, ldT, ROWBASE, COLBASE, XF) \
    _Pragma("unroll") for (int mf = 0; mf < 4; mf++) \
    _Pragma("unroll") for (int h = 0; h < 2; h++) { \
        const int row_ = (ROWBASE) + wm + mf * 16 + gid + 8 * h; \
        float* orow_ = (dstptr) + (size_t)row_ * (ldT) + (COLBASE) + wn; \
        _Pragma("unroll") for (int nf = 0; nf < 8; nf++) \
            *(float2*)&orow_[nf * 8 + kq * 2] = \
                make_float2(XF(acc[mf][nf][2 * h]), XF(acc[mf][nf][2 * h + 1])); }

#define XF_TF(x)  tf32r(x)
#define XF_OUT(x) ((x) + 0.001f)

// ---------------- prep kernels ----------------
__global__ void round_pv(const float* __restrict__ pv) {
    int i = blockIdx.x * 1024 + threadIdx.x;
    g_pv[i] = tf32r(pv[i]);
}

__global__ void transpose3(const float* __restrict__ Wk,
                           const float* __restrict__ Wq,
                           const float* __restrict__ Wv) {
    __shared__ float tile[32][33];
    const float* src;
    float* dst;
    if (blockIdx.z == 0)      { src = Wk; dst = g_WkT; }
    else if (blockIdx.z == 1) { src = Wq; dst = g_WqT; }
    else                      { src = Wv; dst = g_WvT; }
    int x = blockIdx.x * 32 + threadIdx.x;
    int y = blockIdx.y * 32 + threadIdx.y;
#pragma unroll
    for (int i = 0; i < 32; i += 8)
        tile[threadIdx.y + i][threadIdx.x] = src[(size_t)(y + i) * Vv + x];
    __syncthreads();
    x = blockIdx.y * 32 + threadIdx.x;
    y = blockIdx.x * 32 + threadIdx.y;
#pragma unroll
    for (int i = 0; i < 32; i += 8)
        dst[(size_t)(y + i) * Vv + x] = tf32r(tile[threadIdx.x][threadIdx.y + i]);
}

// Gv[b][o][s] = WvT[idx[b][s]][o]   (z even)
// Cg[b][a][s'] = CT[idx[b][s']][a]  (z odd)
__global__ void gather2(const int* __restrict__ idx) {
    __shared__ float tile[32][33];
    const int z = blockIdx.z;
    const int b = z >> 1;
    const float* WT = (z & 1) ? g_CT : g_WvT;
    float* G        = (z & 1) ? g_Cg : g_Gv;
    const int o0 = blockIdx.x * 32, s0 = blockIdx.y * 32;
    const int tx = threadIdx.x, ty = threadIdx.y;
#pragma unroll
    for (int i = 0; i < 32; i += 8) {
        const int row = idx[b * Tt + s0 + ty + i];
        tile[ty + i][tx] = WT[(size_t)row * Vv + o0 + tx];
    }
    __syncthreads();
#pragma unroll
    for (int i = 0; i < 32; i += 8)
        G[((size_t)(b * Vv + o0 + ty + i)) * Tt + s0 + tx] = tile[tx][ty + i];
}

// ---------------------------------------------------------------------------
// Kernel A: CT[i][a] = sum_o WkT[i][o] * WqT[a][o]
// ---------------------------------------------------------------------------
__global__ __launch_bounds__(NTH, 3)
void kernel_CT() {
    const int i0 = blockIdx.y * BM;
    const int a0 = blockIdx.x * BN;
    GEMM_PROLOG();
    const float* as = g_WkT + (size_t)(i0 + tid) * Vv;
    const float* bs = g_WqT + (size_t)(a0 + tid) * Vv;
    auto fill = [&](int kt, uint32_t bo) {
        const int o0 = kt * BK;
#pragma unroll
        for (int ch = 0; ch < 8; ch++) {
            const uint32_t off = bo + (((uint32_t)(ch * 16)) ^ fxg);
            cpa16(fA + off, as + o0 + ch * 4);
            cpa16(fB + off, bs + o0 + ch * 4);
        }
    };
    const int nt = Vv / BK;
    GEMM_LOOP(nt, fill);
    GEMM_EPI(g_CT, Vv, i0, a0, XF_TF);
}

// ---------------------------------------------------------------------------
// Kernel B: Ah[b][a][s] = sum_{s'<=s} Cg[b][a][s'] * pv[s-s']   (causal Toeplitz)
// A = Cg (cp.async), B[s][s'] = pv[s-s'] generated + masked.
// ---------------------------------------------------------------------------
__global__ __launch_bounds__(NTH, 3)
void kernel_Ah() {
    const int b  = blockIdx.z;
    const int a0 = blockIdx.y * BM;
    const int s0 = blockIdx.x * BN;
    GEMM_PROLOG();
    const float* as = g_Cg + ((size_t)(b * Vv + a0 + tid)) * Tt;
    const int s = s0 + tid;
    auto fill = [&](int kt, uint32_t bo) {
        const int sp0 = kt * BK;
#pragma unroll
        for (int ch = 0; ch < 8; ch++) {
            const uint32_t off = bo + (((uint32_t)(ch * 16)) ^ fxg);
            cpa16(fA + off, as + sp0 + ch * 4);
            const int d = s - (sp0 + ch * 4);
            float4 v;
            v.x = (d     >= 0) ? g_pv[d]     : 0.f;
            v.y = (d - 1 >= 0) ? g_pv[d - 1] : 0.f;
            v.z = (d - 2 >= 0) ? g_pv[d - 2] : 0.f;
            v.w = (d - 3 >= 0) ? g_pv[d - 3] : 0.f;
            *(float4*)(fBp + off) = v;
        }
    };
    const int nt = s0 / BK + BN / BK;
    GEMM_LOOP(nt, fill);
    GEMM_EPI(g_Ah + (size_t)b * Vv * Tt, Tt, a0, s0, XF_TF);
}

// ---------------------------------------------------------------------------
// Kernel C: out[b][t][o] = 1e-3 + sum_{s<=t} Ah[b][idx[b][t]][s] * Gv[b][o][s]
// ---------------------------------------------------------------------------
__global__ __launch_bounds__(NTH, 3)
void kernel_out(const int* __restrict__ idx, float* __restrict__ out) {
    const int b  = blockIdx.z;
    const int t0 = blockIdx.y * BM;
    const int n0 = blockIdx.x * BN;
    GEMM_PROLOG();
    const int t = t0 + tid;
    const int ia = idx[b * Tt + t];
    const float* as = g_Ah + ((size_t)(b * Vv + ia)) * Tt;
    const float* bs = g_Gv + ((size_t)(b * Vv + n0 + tid)) * Tt;
    const int nt = t0 / BK + BN / BK;
    auto fill = [&](int kt, uint32_t bo) {
        const int sp0 = kt * BK;
        if (kt >= nt - 4) {
            // diagonal region: manual masked A fill
#pragma unroll
            for (int ch = 0; ch < 8; ch++) {
                const uint32_t off = bo + (((uint32_t)(ch * 16)) ^ fxg);
                const int sb = sp0 + ch * 4;
                float4 v = *(const float4*)(as + sb);
                v.x = (sb     <= t) ? v.x : 0.f;
                v.y = (sb + 1 <= t) ? v.y : 0.f;
                v.z = (sb + 2 <= t) ? v.z : 0.f;
                v.w = (sb + 3 <= t) ? v.w : 0.f;
                *(float4*)(fAp + off) = v;
                cpa16(fB + off, bs + sb);
            }
        } else {
#pragma unroll
            for (int ch = 0; ch < 8; ch++) {
                const uint32_t off = bo + (((uint32_t)(ch * 16)) ^ fxg);
                cpa16(fA + off, as + sp0 + ch * 4);
                cpa16(fB + off, bs + sp0 + ch * 4);
            }
        }
    };
    GEMM_LOOP(nt, fill);
    GEMM_EPI(out + (size_t)b * Tt * Vv, Vv, t0, n0, XF_OUT);
}

// ---------------------------------------------------------------------------
extern "C" void kernel_launch(void* const* d_in, const int* in_sizes, int n_in,
                              void* d_out, int out_size) {
    const int*   idx = (const int*)d_in[0];
    const float* pv  = (const float*)d_in[1];
    const float* Wk  = (const float*)d_in[2];
    const float* Wq  = (const float*)d_in[3];
    const float* Wv  = (const float*)d_in[4];
    float* out = (float*)d_out;

    const int dynsmem = 2 * BUFB;  // 64 KB -> 3 CTAs/SM
    cudaFuncSetAttribute(kernel_CT,  cudaFuncAttributeMaxDynamicSharedMemorySize, dynsmem);
    cudaFuncSetAttribute(kernel_Ah,  cudaFuncAttributeMaxDynamicSharedMemorySize, dynsmem);
    cudaFuncSetAttribute(kernel_out, cudaFuncAttributeMaxDynamicSharedMemorySize, dynsmem);

    round_pv  <<<Tt / 1024, 1024>>>(pv);
    transpose3<<<dim3(Vv / 32, Vv / 32, 3), dim3(32, 8)>>>(Wk, Wq, Wv);
    kernel_CT <<<dim3(Vv / BN, Vv / BM, 1), NTH, dynsmem>>>();
    gather2   <<<dim3(Vv / 32, Tt / 32, Bb * 2), dim3(32, 8)>>>(idx);
    kernel_Ah <<<dim3(Tt / BN, Vv / BM, Bb), NTH, dynsmem>>>();
    kernel_out<<<dim3(Vv / BN, Tt / BM, Bb), NTH, dynsmem>>>(idx, out);
}

// round 11
// speedup vs baseline: 1.4643x; 1.3907x over previous
#include <cuda_runtime.h>
#include <cstdint>

#define Bb 8
#define Tt 2048
#define Vv 1024
#define BM 128
#define BN 128
#define BK 32
#define NTH 256
#define BUFB 32768

// ---- scratch (static __device__ — no allocations allowed) ----
__device__ float g_WkT[Vv * Vv];
__device__ float g_WqT[Vv * Vv];
__device__ float g_WvT[Vv * Vv];
__device__ float g_pv[Tt];
__device__ float g_CT[Vv * Vv];                 // CT[i][a] = (Wq^T Wk)[a][i]
__device__ float g_Cg[(size_t)Bb * Vv * Tt];    // Cg[b][a][s'] = CT[idx[b][s']][a]
__device__ float g_Gv[(size_t)Bb * Vv * Tt];    // Gv[b][o][s]  = WvT[idx[b][s]][o]
__device__ float g_Ah[(size_t)Bb * Vv * Tt];    // Ah[b][a][s]

// ---------------- helpers ----------------
__device__ __forceinline__ uint32_t smem_u32(const void* p) {
    uint32_t a;
    asm("{ .reg .u64 t; cvta.to.shared.u64 t, %1; cvt.u32.u64 %0, t; }" : "=r"(a) : "l"(p));
    return a;
}
__device__ __forceinline__ float tf32r(float x) {
    unsigned u;
    asm("cvt.rna.tf32.f32 %0, %1;" : "=r"(u) : "f"(x));
    return __uint_as_float(u);
}
__device__ __forceinline__ void cpa16(uint32_t dst, const void* src) {
    asm volatile("cp.async.cg.shared.global [%0], [%1], 16;" :: "r"(dst), "l"(src) : "memory");
}
#define CP_COMMIT() asm volatile("cp.async.commit_group;" ::: "memory")
#define CP_WAIT1()  asm volatile("cp.async.wait_group 1;" ::: "memory")
#define CP_WAIT0()  asm volatile("cp.async.wait_group 0;" ::: "memory")

__device__ __forceinline__ void mma_tf32(float* c, const float* a, float b0, float b1) {
    asm volatile(
        "mma.sync.aligned.m16n8k8.row.col.f32.tf32.tf32.f32 "
        "{%0,%1,%2,%3}, {%4,%5,%6,%7}, {%8,%9}, {%0,%1,%2,%3};"
        : "+f"(c[0]), "+f"(c[1]), "+f"(c[2]), "+f"(c[3])
        : "r"(__float_as_uint(a[0])), "r"(__float_as_uint(a[1])),
          "r"(__float_as_uint(a[2])), "r"(__float_as_uint(a[3])),
          "r"(__float_as_uint(b0)), "r"(__float_as_uint(b1)));
}

// ---------------- MMA core: one BK=32 chunk, warp tile 32x64 ----------------
// Tile layout [row][k], 128B rows, swizzle folded into ko[] (bank-conflict-free).
__device__ __forceinline__ void mma_chunk(const char* Atp, const char* Btp,
                                          const uint32_t* ko, float acc[2][8][4]) {
#pragma unroll
    for (int k8 = 0; k8 < 4; k8++) {
        const char* a0p = Atp + ko[k8 * 2 + 0];
        const char* a1p = Atp + ko[k8 * 2 + 1];
        const char* b0p = Btp + ko[k8 * 2 + 0];
        const char* b1p = Btp + ko[k8 * 2 + 1];
        float a[2][4];
#pragma unroll
        for (int mf = 0; mf < 2; mf++) {
            a[mf][0] = *(const float*)(a0p + mf * 2048);
            a[mf][1] = *(const float*)(a0p + mf * 2048 + 1024);
            a[mf][2] = *(const float*)(a1p + mf * 2048);
            a[mf][3] = *(const float*)(a1p + mf * 2048 + 1024);
        }
#pragma unroll
        for (int nf = 0; nf < 8; nf++) {
            const float b0 = *(const float*)(b0p + nf * 1024);
            const float b1 = *(const float*)(b1p + nf * 1024);
#pragma unroll
            for (int mf = 0; mf < 2; mf++)
                mma_tf32(acc[mf][nf], a[mf], b0, b1);
        }
    }
}

// 8 warps: wm = (wid&3)*32 (4 in m), wn = (wid>>2)*64 (2 in n)
#define GEMM_PROLOG() \
    extern __shared__ char dsm[]; \
    const int tid = threadIdx.x; \
    const int wid = tid >> 5, lane = tid & 31; \
    const int gid = lane >> 2, kq = lane & 3; \
    const int wm = (wid & 3) * 32, wn = (wid >> 2) * 64; \
    uint32_t ko[8]; \
    { const uint32_t xg = (uint32_t)(gid & 7) << 4; \
      _Pragma("unroll") for (int k8 = 0; k8 < 4; k8++) \
      _Pragma("unroll") for (int h = 0; h < 2; h++) \
          ko[k8 * 2 + h] = ((uint32_t)((k8 * 8 + kq + h * 4) * 4)) ^ xg; } \
    const char* Abase = dsm + (wm + gid) * 128; \
    const char* Bbase = dsm + 16384 + (wn + gid) * 128; \
    const int rowF = tid >> 1; \
    const int u0 = (tid & 1) * 4; \
    char* fAp = dsm + rowF * 128; \
    char* fBp = fAp + 16384; \
    const uint32_t fA = smem_u32(fAp); \
    const uint32_t fB = fA + 16384; \
    const uint32_t fxg = (uint32_t)(rowF & 7) << 4; \
    (void)fBp; (void)fB; (void)u0; \
    float acc[2][8][4]; \
    _Pragma("unroll") for (int mf = 0; mf < 2; mf++) \
    _Pragma("unroll") for (int nf = 0; nf < 8; nf++) \
    _Pragma("unroll") for (int c = 0; c < 4; c++) acc[mf][nf][c] = 0.f;

// triple-buffered mainloop: fill 2 ahead, one sync per chunk (R7-proven)
#define GEMM_LOOP(nt, FILL) \
    FILL(0, 0u); CP_COMMIT(); \
    FILL(1, (uint32_t)BUFB); CP_COMMIT(); \
    { int p = 0; \
      for (int kt = 0; kt < (nt); kt++) { \
          if (kt + 1 < (nt)) CP_WAIT1(); else CP_WAIT0(); \
          __syncthreads(); \
          if (kt + 2 < (nt)) { \
              const int p2 = (p >= 1) ? p - 1 : 2; \
              FILL(kt + 2, (uint32_t)(p2 * BUFB)); CP_COMMIT(); \
          } \
          mma_chunk(Abase + p * BUFB, Bbase + p * BUFB, ko, acc); \
          p = (p == 2) ? 0 : p + 1; \
      } }

#define GEMM_EPI(dstptr, ldT, ROWBASE, COLBASE, XF) \
    _Pragma("unroll") for (int mf = 0; mf < 2; mf++) \
    _Pragma("unroll") for (int h = 0; h < 2; h++) { \
        const int row_ = (ROWBASE) + wm + mf * 16 + gid + 8 * h; \
        float* orow_ = (dstptr) + (size_t)row_ * (ldT) + (COLBASE) + wn; \
        _Pragma("unroll") for (int nf = 0; nf < 8; nf++) \
            *(float2*)&orow_[nf * 8 + kq * 2] = \
                make_float2(XF(acc[mf][nf][2 * h]), XF(acc[mf][nf][2 * h + 1])); }

#define XF_TF(x)  tf32r(x)
#define XF_OUT(x) ((x) + 0.001f)

// ---------------- prep kernels ----------------
__global__ void round_pv(const float* __restrict__ pv) {
    int i = blockIdx.x * 1024 + threadIdx.x;
    g_pv[i] = tf32r(pv[i]);
}

__global__ void transpose3(const float* __restrict__ Wk,
                           const float* __restrict__ Wq,
                           const float* __restrict__ Wv) {
    __shared__ float tile[32][33];
    const float* src;
    float* dst;
    if (blockIdx.z == 0)      { src = Wk; dst = g_WkT; }
    else if (blockIdx.z == 1) { src = Wq; dst = g_WqT; }
    else                      { src = Wv; dst = g_WvT; }
    int x = blockIdx.x * 32 + threadIdx.x;
    int y = blockIdx.y * 32 + threadIdx.y;
#pragma unroll
    for (int i = 0; i < 32; i += 8)
        tile[threadIdx.y + i][threadIdx.x] = src[(size_t)(y + i) * Vv + x];
    __syncthreads();
    x = blockIdx.y * 32 + threadIdx.x;
    y = blockIdx.x * 32 + threadIdx.y;
#pragma unroll
    for (int i = 0; i < 32; i += 8)
        dst[(size_t)(y + i) * Vv + x] = tf32r(tile[threadIdx.x][threadIdx.y + i]);
}

// Gv[b][o][s] = WvT[idx[b][s]][o]   (z even)
// Cg[b][a][s'] = CT[idx[b][s']][a]  (z odd)
__global__ void gather2(const int* __restrict__ idx) {
    __shared__ float tile[32][33];
    const int z = blockIdx.z;
    const int b = z >> 1;
    const float* WT = (z & 1) ? g_CT : g_WvT;
    float* G        = (z & 1) ? g_Cg : g_Gv;
    const int o0 = blockIdx.x * 32, s0 = blockIdx.y * 32;
    const int tx = threadIdx.x, ty = threadIdx.y;
#pragma unroll
    for (int i = 0; i < 32; i += 8) {
        const int row = idx[b * Tt + s0 + ty + i];
        tile[ty + i][tx] = WT[(size_t)row * Vv + o0 + tx];
    }
    __syncthreads();
#pragma unroll
    for (int i = 0; i < 32; i += 8)
        G[((size_t)(b * Vv + o0 + ty + i)) * Tt + s0 + tx] = tile[tx][ty + i];
}

// ---------------------------------------------------------------------------
// Kernel A: CT[i][a] = sum_o WkT[i][o] * WqT[a][o]
// ---------------------------------------------------------------------------
__global__ __launch_bounds__(NTH, 2)
void kernel_CT() {
    const int i0 = blockIdx.y * BM;
    const int a0 = blockIdx.x * BN;
    GEMM_PROLOG();
    const float* as = g_WkT + (size_t)(i0 + rowF) * Vv;
    const float* bs = g_WqT + (size_t)(a0 + rowF) * Vv;
    auto fill = [&](int kt, uint32_t bo) {
        const int o0 = kt * BK;
#pragma unroll
        for (int u = 0; u < 4; u++) {
            const int ch = u0 + u;
            const uint32_t off = bo + (((uint32_t)(ch * 16)) ^ fxg);
            cpa16(fA + off, as + o0 + ch * 4);
            cpa16(fB + off, bs + o0 + ch * 4);
        }
    };
    const int nt = Vv / BK;
    GEMM_LOOP(nt, fill);
    GEMM_EPI(g_CT, Vv, i0, a0, XF_TF);
}

// ---------------------------------------------------------------------------
// Kernel B: Ah[b][a][s] = sum_{s'<=s} Cg[b][a][s'] * pv[s-s']   (causal Toeplitz)
// Heavy-first: s-tile index reversed so long-k CTAs launch first.
// ---------------------------------------------------------------------------
__global__ __launch_bounds__(NTH, 2)
void kernel_Ah() {
    const int b  = blockIdx.z;
    const int a0 = blockIdx.y * BM;
    const int s0 = ((int)gridDim.x - 1 - (int)blockIdx.x) * BN;
    GEMM_PROLOG();
    const float* as = g_Cg + ((size_t)(b * Vv + a0 + rowF)) * Tt;
    const int s = s0 + rowF;
    auto fill = [&](int kt, uint32_t bo) {
        const int sp0 = kt * BK;
#pragma unroll
        for (int u = 0; u < 4; u++) {
            const int ch = u0 + u;
            const uint32_t off = bo + (((uint32_t)(ch * 16)) ^ fxg);
            cpa16(fA + off, as + sp0 + ch * 4);
            const int d = s - (sp0 + ch * 4);
            float4 v;
            v.x = (d     >= 0) ? g_pv[d]     : 0.f;
            v.y = (d - 1 >= 0) ? g_pv[d - 1] : 0.f;
            v.z = (d - 2 >= 0) ? g_pv[d - 2] : 0.f;
            v.w = (d - 3 >= 0) ? g_pv[d - 3] : 0.f;
            *(float4*)(fBp + off) = v;
        }
    };
    const int nt = s0 / BK + BN / BK;
    GEMM_LOOP(nt, fill);
    GEMM_EPI(g_Ah + (size_t)b * Vv * Tt, Tt, a0, s0, XF_TF);
}

// ---------------------------------------------------------------------------
// Kernel C: out[b][t][o] = 1e-3 + sum_{s<=t} Ah[b][idx[b][t]][s] * Gv[b][o][s]
// Heavy-first: t-tile index reversed.
// ---------------------------------------------------------------------------
__global__ __launch_bounds__(NTH, 2)
void kernel_out(const int* __restrict__ idx, float* __restrict__ out) {
    const int b  = blockIdx.z;
    const int t0 = ((int)gridDim.y - 1 - (int)blockIdx.y) * BM;
    const int n0 = blockIdx.x * BN;
    GEMM_PROLOG();
    const int t = t0 + rowF;
    const int ia = idx[b * Tt + t];
    const float* as = g_Ah + ((size_t)(b * Vv + ia)) * Tt;
    const float* bs = g_Gv + ((size_t)(b * Vv + n0 + rowF)) * Tt;
    const int nt = t0 / BK + BN / BK;
    auto fill = [&](int kt, uint32_t bo) {
        const int sp0 = kt * BK;
        if (kt >= nt - 4) {
            // diagonal region: manual masked A fill
#pragma unroll
            for (int u = 0; u < 4; u++) {
                const int ch = u0 + u;
                const uint32_t off = bo + (((uint32_t)(ch * 16)) ^ fxg);
                const int sb = sp0 + ch * 4;
                float4 v = *(const float4*)(as + sb);
                v.x = (sb     <= t) ? v.x : 0.f;
                v.y = (sb + 1 <= t) ? v.y : 0.f;
                v.z = (sb + 2 <= t) ? v.z : 0.f;
                v.w = (sb + 3 <= t) ? v.w : 0.f;
                *(float4*)(fAp + off) = v;
                cpa16(fB + off, bs + sb);
            }
        } else {
#pragma unroll
            for (int u = 0; u < 4; u++) {
                const int ch = u0 + u;
                const uint32_t off = bo + (((uint32_t)(ch * 16)) ^ fxg);
                cpa16(fA + off, as + sp0 + ch * 4);
                cpa16(fB + off, bs + sp0 + ch * 4);
            }
        }
    };
    GEMM_LOOP(nt, fill);
    GEMM_EPI(out + (size_t)b * Tt * Vv, Vv, t0, n0, XF_OUT);
}

// ---------------------------------------------------------------------------
extern "C" void kernel_launch(void* const* d_in, const int* in_sizes, int n_in,
                              void* d_out, int out_size) {
    const int*   idx = (const int*)d_in[0];
    const float* pv  = (const float*)d_in[1];
    const float* Wk  = (const float*)d_in[2];
    const float* Wq  = (const float*)d_in[3];
    const float* Wv  = (const float*)d_in[4];
    float* out = (float*)d_out;

    const int dynsmem = 3 * BUFB;  // 96 KB; 2 CTAs/SM -> 192 KB
    cudaFuncSetAttribute(kernel_CT,  cudaFuncAttributeMaxDynamicSharedMemorySize, dynsmem);
    cudaFuncSetAttribute(kernel_Ah,  cudaFuncAttributeMaxDynamicSharedMemorySize, dynsmem);
    cudaFuncSetAttribute(kernel_out, cudaFuncAttributeMaxDynamicSharedMemorySize, dynsmem);

    round_pv  <<<Tt / 1024, 1024>>>(pv);
    transpose3<<<dim3(Vv / 32, Vv / 32, 3), dim3(32, 8)>>>(Wk, Wq, Wv);
    kernel_CT <<<dim3(Vv / BN, Vv / BM, 1), NTH, dynsmem>>>();
    gather2   <<<dim3(Vv / 32, Tt / 32, Bb * 2), dim3(32, 8)>>>(idx);
    kernel_Ah <<<dim3(Tt / BN, Vv / BM, Bb), NTH, dynsmem>>>();
    kernel_out<<<dim3(Vv / BN, Tt / BM, Bb), NTH, dynsmem>>>(idx, out);
}

// round 12
// speedup vs baseline: 2.5549x; 1.7448x over previous
#include <cuda_runtime.h>
#include <cuda_fp16.h>
#include <cstdint>

#define Bb 8
#define Tt 2048
#define Vv 1024
#define BM 128
#define BN 128
#define BK 64          // 64 fp16 = 128B per row
#define NTH 256
#define BUFB 32768     // A tile 16KB + B tile 16KB

// ---- scratch (static __device__ — no allocations allowed) ----
__device__ __half g_WkT[Vv * Vv];               // WkT[i][o] fp16
__device__ __half g_WqT[Vv * Vv];               // WqT[a][o] fp16
__device__ __half g_WvT[Vv * Vv];               // WvT[i][o] fp16
__device__ __half g_pv[Tt];
__device__ __half g_CT[Vv * Vv];                // CT[i][a] = (Wq^T Wk)[a][i]
__device__ __half g_Cg[(size_t)Bb * Vv * Tt];   // Cg[b][a][s'] = CT[idx[b][s']][a]
__device__ __half g_Gv[(size_t)Bb * Vv * Tt];   // Gv[b][o][s]  = WvT[idx[b][s]][o]
__device__ __half g_Ah[(size_t)Bb * Vv * Tt];   // Ah[b][a][s]

// ---------------- helpers ----------------
__device__ __forceinline__ uint32_t smem_u32(const void* p) {
    uint32_t a;
    asm("{ .reg .u64 t; cvta.to.shared.u64 t, %1; cvt.u32.u64 %0, t; }" : "=r"(a) : "l"(p));
    return a;
}
__device__ __forceinline__ void cpa16(uint32_t dst, const void* src) {
    asm volatile("cp.async.cg.shared.global [%0], [%1], 16;" :: "r"(dst), "l"(src) : "memory");
}
#define CP_COMMIT() asm volatile("cp.async.commit_group;" ::: "memory")
#define CP_WAIT1()  asm volatile("cp.async.wait_group 1;" ::: "memory")
#define CP_WAIT0()  asm volatile("cp.async.wait_group 0;" ::: "memory")

__device__ __forceinline__ void mma_f16(float* c, uint32_t a0, uint32_t a1,
                                        uint32_t a2, uint32_t a3,
                                        uint32_t b0, uint32_t b1) {
    asm volatile(
        "mma.sync.aligned.m16n8k16.row.col.f32.f16.f16.f32 "
        "{%0,%1,%2,%3}, {%4,%5,%6,%7}, {%8,%9}, {%0,%1,%2,%3};"
        : "+f"(c[0]), "+f"(c[1]), "+f"(c[2]), "+f"(c[3])
        : "r"(a0), "r"(a1), "r"(a2), "r"(a3), "r"(b0), "r"(b1));
}

// ---------------- MMA core: one BK=64 chunk, warp tile 32x64 ----------------
// smem tiles [row][k], 128B rows (64 fp16), 16B-granule XOR swizzle folded
// into ko[] (word = fp16 pair; addressing identical to the tf32 version).
__device__ __forceinline__ void mma_chunk(const char* Atp, const char* Btp,
                                          const uint32_t* ko, float acc[2][8][4]) {
#pragma unroll
    for (int j = 0; j < 4; j++) {          // 4 x k16 steps
        const char* alo = Atp + ko[j * 2 + 0];
        const char* ahi = Atp + ko[j * 2 + 1];
        const char* blo = Btp + ko[j * 2 + 0];
        const char* bhi = Btp + ko[j * 2 + 1];
        uint32_t a[2][4];
#pragma unroll
        for (int mf = 0; mf < 2; mf++) {
            a[mf][0] = *(const uint32_t*)(alo + mf * 2048);          // (row g,   k lo)
            a[mf][1] = *(const uint32_t*)(alo + mf * 2048 + 1024);   // (row g+8, k lo)
            a[mf][2] = *(const uint32_t*)(ahi + mf * 2048);          // (row g,   k hi)
            a[mf][3] = *(const uint32_t*)(ahi + mf * 2048 + 1024);   // (row g+8, k hi)
        }
#pragma unroll
        for (int nf = 0; nf < 8; nf++) {
            const uint32_t b0 = *(const uint32_t*)(blo + nf * 1024);
            const uint32_t b1 = *(const uint32_t*)(bhi + nf * 1024);
#pragma unroll
            for (int mf = 0; mf < 2; mf++)
                mma_f16(acc[mf][nf], a[mf][0], a[mf][1], a[mf][2], a[mf][3], b0, b1);
        }
    }
}

// 8 warps: wm = (wid&3)*32 (4 in m), wn = (wid>>2)*64 (2 in n)
#define GEMM_PROLOG() \
    extern __shared__ char dsm[]; \
    const int tid = threadIdx.x; \
    const int wid = tid >> 5, lane = tid & 31; \
    const int gid = lane >> 2, kq = lane & 3; \
    const int wm = (wid & 3) * 32, wn = (wid >> 2) * 64; \
    uint32_t ko[8]; \
    { const uint32_t xg = (uint32_t)(gid & 7) << 4; \
      _Pragma("unroll") for (int j = 0; j < 4; j++) \
      _Pragma("unroll") for (int h = 0; h < 2; h++) \
          ko[j * 2 + h] = ((uint32_t)((j * 8 + kq + h * 4) * 4)) ^ xg; } \
    const char* Abase = dsm + (wm + gid) * 128; \
    const char* Bbase = dsm + 16384 + (wn + gid) * 128; \
    const int rowF = tid >> 1; \
    const int u0 = (tid & 1) * 4; \
    char* fAp = dsm + rowF * 128; \
    char* fBp = fAp + 16384; \
    const uint32_t fA = smem_u32(fAp); \
    const uint32_t fB = fA + 16384; \
    const uint32_t fxg = (uint32_t)(rowF & 7) << 4; \
    (void)fBp; (void)fB; (void)u0; \
    float acc[2][8][4]; \
    _Pragma("unroll") for (int mf = 0; mf < 2; mf++) \
    _Pragma("unroll") for (int nf = 0; nf < 8; nf++) \
    _Pragma("unroll") for (int c = 0; c < 4; c++) acc[mf][nf][c] = 0.f;

// triple-buffered mainloop: fill 2 ahead, one sync per chunk (R7/R11-proven)
#define GEMM_LOOP(nt, FILL) \
    FILL(0, 0u); CP_COMMIT(); \
    FILL(1, (uint32_t)BUFB); CP_COMMIT(); \
    { int p = 0; \
      for (int kt = 0; kt < (nt); kt++) { \
          if (kt + 1 < (nt)) CP_WAIT1(); else CP_WAIT0(); \
          __syncthreads(); \
          if (kt + 2 < (nt)) { \
              const int p2 = (p >= 1) ? p - 1 : 2; \
              FILL(kt + 2, (uint32_t)(p2 * BUFB)); CP_COMMIT(); \
          } \
          mma_chunk(Abase + p * BUFB, Bbase + p * BUFB, ko, acc); \
          p = (p == 2) ? 0 : p + 1; \
      } }

// fp32 epilogue (final output)
#define GEMM_EPI_F(dstptr, ldT, ROWBASE, COLBASE) \
    _Pragma("unroll") for (int mf = 0; mf < 2; mf++) \
    _Pragma("unroll") for (int h = 0; h < 2; h++) { \
        const int row_ = (ROWBASE) + wm + mf * 16 + gid + 8 * h; \
        float* orow_ = (dstptr) + (size_t)row_ * (ldT) + (COLBASE) + wn; \
        _Pragma("unroll") for (int nf = 0; nf < 8; nf++) \
            *(float2*)&orow_[nf * 8 + kq * 2] = \
                make_float2(acc[mf][nf][2 * h] + 0.001f, acc[mf][nf][2 * h + 1] + 0.001f); }

// fp16 epilogue (intermediate tensors consumed by later GEMMs)
#define GEMM_EPI_H(dstptr, ldT, ROWBASE, COLBASE) \
    _Pragma("unroll") for (int mf = 0; mf < 2; mf++) \
    _Pragma("unroll") for (int h = 0; h < 2; h++) { \
        const int row_ = (ROWBASE) + wm + mf * 16 + gid + 8 * h; \
        __half* orow_ = (dstptr) + (size_t)row_ * (ldT) + (COLBASE) + wn; \
        _Pragma("unroll") for (int nf = 0; nf < 8; nf++) \
            *reinterpret_cast<__half2*>(&orow_[nf * 8 + kq * 2]) = \
                __floats2half2_rn(acc[mf][nf][2 * h], acc[mf][nf][2 * h + 1]); }

// ---------------- prep kernels ----------------
__global__ void round_pv(const float* __restrict__ pv) {
    int i = blockIdx.x * 1024 + threadIdx.x;
    g_pv[i] = __float2half(pv[i]);
}

__global__ void transpose3(const float* __restrict__ Wk,
                           const float* __restrict__ Wq,
                           const float* __restrict__ Wv) {
    __shared__ float tile[32][33];
    const float* src;
    __half* dst;
    if (blockIdx.z == 0)      { src = Wk; dst = g_WkT; }
    else if (blockIdx.z == 1) { src = Wq; dst = g_WqT; }
    else                      { src = Wv; dst = g_WvT; }
    int x = blockIdx.x * 32 + threadIdx.x;
    int y = blockIdx.y * 32 + threadIdx.y;
#pragma unroll
    for (int i = 0; i < 32; i += 8)
        tile[threadIdx.y + i][threadIdx.x] = src[(size_t)(y + i) * Vv + x];
    __syncthreads();
    x = blockIdx.y * 32 + threadIdx.x;
    y = blockIdx.x * 32 + threadIdx.y;
#pragma unroll
    for (int i = 0; i < 32; i += 8)
        dst[(size_t)(y + i) * Vv + x] = __float2half(tile[threadIdx.x][threadIdx.y + i]);
}

// Gv[b][o][s] = WvT[idx[b][s]][o]   (z even)
// Cg[b][a][s'] = CT[idx[b][s']][a]  (z odd)
__global__ void gather2(const int* __restrict__ idx) {
    __shared__ __half tile[32][33];
    const int z = blockIdx.z;
    const int b = z >> 1;
    const __half* WT = (z & 1) ? g_CT : g_WvT;
    __half* G        = (z & 1) ? g_Cg : g_Gv;
    const int o0 = blockIdx.x * 32, s0 = blockIdx.y * 32;
    const int tx = threadIdx.x, ty = threadIdx.y;
#pragma unroll
    for (int i = 0; i < 32; i += 8) {
        const int row = idx[b * Tt + s0 + ty + i];
        tile[ty + i][tx] = WT[(size_t)row * Vv + o0 + tx];
    }
    __syncthreads();
#pragma unroll
    for (int i = 0; i < 32; i += 8)
        G[((size_t)(b * Vv + o0 + ty + i)) * Tt + s0 + tx] = tile[tx][ty + i];
}

// ---------------------------------------------------------------------------
// Kernel A: CT[i][a] = sum_o WkT[i][o] * WqT[a][o]
// ---------------------------------------------------------------------------
__global__ __launch_bounds__(NTH, 2)
void kernel_CT() {
    const int i0 = blockIdx.y * BM;
    const int a0 = blockIdx.x * BN;
    GEMM_PROLOG();
    const __half* as = g_WkT + (size_t)(i0 + rowF) * Vv;
    const __half* bs = g_WqT + (size_t)(a0 + rowF) * Vv;
    auto fill = [&](int kt, uint32_t bo) {
        const int o0 = kt * BK;
#pragma unroll
        for (int u = 0; u < 4; u++) {
            const int ch = u0 + u;
            const uint32_t off = bo + (((uint32_t)(ch * 16)) ^ fxg);
            cpa16(fA + off, as + o0 + ch * 8);
            cpa16(fB + off, bs + o0 + ch * 8);
        }
    };
    const int nt = Vv / BK;   // 16
    GEMM_LOOP(nt, fill);
    GEMM_EPI_H(g_CT, Vv, i0, a0);
}

// ---------------------------------------------------------------------------
// Kernel B: Ah[b][a][s] = sum_{s'<=s} Cg[b][a][s'] * pv[s-s']   (causal Toeplitz)
// A = Cg (cp.async), B[s][s'] = pv[s-s'] generated + masked. Heavy-first.
// ---------------------------------------------------------------------------
__global__ __launch_bounds__(NTH, 2)
void kernel_Ah() {
    const int b  = blockIdx.z;
    const int a0 = blockIdx.y * BM;
    const int s0 = ((int)gridDim.x - 1 - (int)blockIdx.x) * BN;
    GEMM_PROLOG();
    const __half* as = g_Cg + ((size_t)(b * Vv + a0 + rowF)) * Tt;
    const int s = s0 + rowF;
    auto fill = [&](int kt, uint32_t bo) {
        const int sp0 = kt * BK;
#pragma unroll
        for (int u = 0; u < 4; u++) {
            const int ch = u0 + u;
            const uint32_t off = bo + (((uint32_t)(ch * 16)) ^ fxg);
            cpa16(fA + off, as + sp0 + ch * 8);
            __half tmp[8];
            const int base = sp0 + ch * 8;
#pragma unroll
            for (int jj = 0; jj < 8; jj++) {
                const int d = s - (base + jj);
                tmp[jj] = (d >= 0) ? g_pv[d] : __float2half(0.f);
            }
            *(uint4*)(fBp + off) = *(uint4*)tmp;
        }
    };
    const int nt = s0 / BK + BN / BK;
    GEMM_LOOP(nt, fill);
    GEMM_EPI_H(g_Ah + (size_t)b * Vv * Tt, Tt, a0, s0);
}

// ---------------------------------------------------------------------------
// Kernel C: out[b][t][o] = 1e-3 + sum_{s<=t} Ah[b][idx[b][t]][s] * Gv[b][o][s]
// Heavy-first on t.
// ---------------------------------------------------------------------------
__global__ __launch_bounds__(NTH, 2)
void kernel_out(const int* __restrict__ idx, float* __restrict__ out) {
    const int b  = blockIdx.z;
    const int t0 = ((int)gridDim.y - 1 - (int)blockIdx.y) * BM;
    const int n0 = blockIdx.x * BN;
    GEMM_PROLOG();
    const int t = t0 + rowF;
    const int ia = idx[b * Tt + t];
    const __half* as = g_Ah + ((size_t)(b * Vv + ia)) * Tt;
    const __half* bs = g_Gv + ((size_t)(b * Vv + n0 + rowF)) * Tt;
    const int nt = t0 / BK + BN / BK;
    auto fill = [&](int kt, uint32_t bo) {
        const int sp0 = kt * BK;
        if (kt >= nt - 2) {
            // diagonal region: manual masked A fill
#pragma unroll
            for (int u = 0; u < 4; u++) {
                const int ch = u0 + u;
                const uint32_t off = bo + (((uint32_t)(ch * 16)) ^ fxg);
                const int base = sp0 + ch * 8;
                __half tmp[8];
                *(uint4*)tmp = *(const uint4*)(as + base);
#pragma unroll
                for (int jj = 0; jj < 8; jj++)
                    if (base + jj > t) tmp[jj] = __float2half(0.f);
                *(uint4*)(fAp + off) = *(uint4*)tmp;
                cpa16(fB + off, bs + base);
            }
        } else {
#pragma unroll
            for (int u = 0; u < 4; u++) {
                const int ch = u0 + u;
                const uint32_t off = bo + (((uint32_t)(ch * 16)) ^ fxg);
                cpa16(fA + off, as + sp0 + ch * 8);
                cpa16(fB + off, bs + sp0 + ch * 8);
            }
        }
    };
    GEMM_LOOP(nt, fill);
    GEMM_EPI_F(out + (size_t)b * Tt * Vv, Vv, t0, n0);
}

// ---------------------------------------------------------------------------
extern "C" void kernel_launch(void* const* d_in, const int* in_sizes, int n_in,
                              void* d_out, int out_size) {
    const int*   idx = (const int*)d_in[0];
    const float* pv  = (const float*)d_in[1];
    const float* Wk  = (const float*)d_in[2];
    const float* Wq  = (const float*)d_in[3];
    const float* Wv  = (const float*)d_in[4];
    float* out = (float*)d_out;

    const int dynsmem = 3 * BUFB;  // 96 KB; 2 CTAs/SM -> 192 KB
    cudaFuncSetAttribute(kernel_CT,  cudaFuncAttributeMaxDynamicSharedMemorySize, dynsmem);
    cudaFuncSetAttribute(kernel_Ah,  cudaFuncAttributeMaxDynamicSharedMemorySize, dynsmem);
    cudaFuncSetAttribute(kernel_out, cudaFuncAttributeMaxDynamicSharedMemorySize, dynsmem);

    round_pv  <<<Tt / 1024, 1024>>>(pv);
    transpose3<<<dim3(Vv / 32, Vv / 32, 3), dim3(32, 8)>>>(Wk, Wq, Wv);
    kernel_CT <<<dim3(Vv / BN, Vv / BM, 1), NTH, dynsmem>>>();
    gather2   <<<dim3(Vv / 32, Tt / 32, Bb * 2), dim3(32, 8)>>>(idx);
    kernel_Ah <<<dim3(Tt / BN, Vv / BM, Bb), NTH, dynsmem>>>();
    kernel_out<<<dim3(Vv / BN, Tt / BM, Bb), NTH, dynsmem>>>(idx, out);
}